// round 12
// baseline (speedup 1.0000x reference)
#include <cuda_runtime.h>
#include <cuda_bf16.h>

// Problem constants (fixed by the dataset instance)
#define N1TOT 65536
#define N2TOT 16384
#define N1PB  16384
#define N2PB  4096
#define CV    192   // Cout*3
#define G     8      // bins per axis
#define NBIN  512    // per batch
#define NBINT 2048   // total (4 batches)
#define BINW  0.125f
#define CAP1  160    // query-bin capacity (Poisson mean 32)
#define CAP2  64     // candidate-bin capacity (Poisson mean 8)

typedef unsigned long long ull;

// Scratch
__device__ float  g_y2t[N2TOT * CV];       // y2 point-major [n][c*3+v]
__device__ int    g_cnt1[NBINT];           // zeroed at end of every call (interp)
__device__ int    g_cnt2[NBINT];
__device__ float4 g_bin1[NBINT][CAP1];     // queries  (x,y,z, orig idx bits)
__device__ float4 g_bin2[NBINT][CAP2];     // cands    (x,y,z, local idx bits)
__device__ float  g_kd[3][N1TOT];
__device__ int    g_ki[3][N1TOT];

// ---- packed fp32x2 helpers (Blackwell) ------------------------------------
__device__ __forceinline__ ull f2fma(ull a, ull b, ull c) {
    ull d; asm("fma.rn.f32x2 %0, %1, %2, %3;" : "=l"(d) : "l"(a), "l"(b), "l"(c));
    return d;
}
__device__ __forceinline__ void f2unpack(ull p, float& lo, float& hi) {
    asm("mov.b64 {%0, %1}, %2;" : "=f"(lo), "=f"(hi) : "l"(p));
}

// ---------------------------------------------------------------------------
// Fused VN linear+leakyrelu (f32x2), DOUBLE-BUFFERED: one __syncthreads per
// K-chunk; STS of chunk c+1 and LDG of chunk c+2 overlap compute of chunk c.
//   blocks [0,512)    : layer2 (x2, CIN=128) -> g_y2t point-major
//   blocks [512,2560) : layer1 (x1, CIN=64)  -> out channel-major
// ---------------------------------------------------------------------------
#define WS2  66                     // ull stride per channel row (w pairs)
#define BUFU (32 * WS2 + 32 * 3 * 32)   // 5184 ull per buffer

__global__ void __launch_bounds__(256, 2) vn_fused_kernel(
    const float* __restrict__ x1, const float* __restrict__ w1f,
    const float* __restrict__ w1d,
    const float* __restrict__ x2, const float* __restrict__ w2f,
    const float* __restrict__ w2d,
    float* __restrict__ out)
{
    extern __shared__ ull smu[];          // 2 * BUFU ull = 82944 B
    const int tid = threadIdx.x;
    const int p  = tid & 31;
    const int og = tid >> 5;
    const bool is2 = blockIdx.x < 512;
    const float* x  = is2 ? x2  : x1;
    const float* wf = is2 ? w2f : w1f;
    const float* wd = is2 ? w2d : w1d;
    const int CIN = is2 ? 128 : 64;
    const int NCH = CIN >> 5;             // chunks
    const int N   = is2 ? N2TOT : N1TOT;
    const int n0  = (is2 ? blockIdx.x : blockIdx.x - 512) * 32;

    ull pd[8][3];
#pragma unroll
    for (int i = 0; i < 8; i++)
#pragma unroll
        for (int v = 0; v < 3; v++) pd[i][v] = 0ull;

    float wfp[8], wdp[8], xp[12];         // prefetch registers

    auto load_regs = [&](int c0) {
#pragma unroll
        for (int j = 0; j < 8; j++) {
            int i = tid + j * 256;
            int o = i >> 5, cc = i & 31;
            wfp[j] = wf[o * CIN + c0 + cc];
            wdp[j] = wd[o * CIN + c0 + cc];
        }
#pragma unroll
        for (int j = 0; j < 12; j++) {
            int i = tid + j * 256;
            int v = i >> 10, cc = (i >> 5) & 31, pp = i & 31;
            xp[j] = x[(size_t)(c0 + cc) * 3 * N + (size_t)v * N + (n0 + pp)];
        }
    };
    auto sts_buf = [&](int buf) {
        float2* wsf2 = (float2*)(smu + (size_t)buf * BUFU);
        float2* xsf2 = (float2*)(smu + (size_t)buf * BUFU + 32 * WS2);
#pragma unroll
        for (int j = 0; j < 8; j++) {
            int i = tid + j * 256;
            int o = i >> 5, cc = i & 31;
            wsf2[cc * WS2 + o] = make_float2(wfp[j], wdp[j]);
        }
#pragma unroll
        for (int j = 0; j < 12; j++) {
            int i = tid + j * 256;
            int v = i >> 10, cc = (i >> 5) & 31, pp = i & 31;
            xsf2[(cc * 3 + v) * 32 + pp] = make_float2(xp[j], xp[j]);
        }
    };

    load_regs(0);
    sts_buf(0);
    if (NCH > 1) load_regs(32);
    __syncthreads();

    int cur = 0;
    for (int c = 0; c < NCH; c++) {
        if (c + 1 < NCH) sts_buf(cur ^ 1);        // chunk c+1 from regs
        if (c + 2 < NCH) load_regs((c + 2) * 32); // prefetch chunk c+2
        const ull* ws = smu + (size_t)cur * BUFU;
        const ull* xs = ws + 32 * WS2;
        const ulonglong2* wsv = (const ulonglong2*)ws;
#pragma unroll 4
        for (int cc = 0; cc < 32; cc++) {
            ull xv0 = xs[(cc * 3 + 0) * 32 + p];
            ull xv1 = xs[(cc * 3 + 1) * 32 + p];
            ull xv2 = xs[(cc * 3 + 2) * 32 + p];
#pragma unroll
            for (int k = 0; k < 4; k++) {
                ulonglong2 w2 = wsv[cc * (WS2 / 2) + og * 4 + k];
                int i = 2 * k;
                pd[i][0]   = f2fma(xv0, w2.x, pd[i][0]);
                pd[i][1]   = f2fma(xv1, w2.x, pd[i][1]);
                pd[i][2]   = f2fma(xv2, w2.x, pd[i][2]);
                pd[i+1][0] = f2fma(xv0, w2.y, pd[i+1][0]);
                pd[i+1][1] = f2fma(xv1, w2.y, pd[i+1][1]);
                pd[i+1][2] = f2fma(xv2, w2.y, pd[i+1][2]);
            }
        }
        __syncthreads();
        cur ^= 1;
    }

    // nonlinearity: dot>=0 -> P ; dot<0 -> P - 0.8*(dot/(|D|^2+1e-6))*D
    float val[8][3];
#pragma unroll
    for (int i = 0; i < 8; i++) {
        float P[3], D[3];
#pragma unroll
        for (int v = 0; v < 3; v++) f2unpack(pd[i][v], P[v], D[v]);
        float dot = P[0] * D[0] + P[1] * D[1] + P[2] * D[2];
        float dd  = D[0] * D[0] + D[1] * D[1] + D[2] * D[2];
        float coef = (dot < 0.f) ? (0.8f * dot / (dd + 1e-6f)) : 0.f;
        val[i][0] = P[0] - coef * D[0];
        val[i][1] = P[1] - coef * D[1];
        val[i][2] = P[2] - coef * D[2];
    }

    if (!is2) {
#pragma unroll
        for (int i = 0; i < 8; i++) {
            int o = og * 8 + i;
#pragma unroll
            for (int v = 0; v < 3; v++)
                out[(size_t)(o * 3 + v) * N + (n0 + p)] = val[i][v];
        }
    } else {
        __syncthreads();
        float* tb = (float*)smu;          // [32][193] transpose buf
#pragma unroll
        for (int i = 0; i < 8; i++) {
            int o = og * 8 + i;
#pragma unroll
            for (int v = 0; v < 3; v++)
                tb[p * 193 + (o * 3 + v)] = val[i][v];
        }
        __syncthreads();
        for (int i = tid; i < 32 * CV; i += 256) {
            int pp = i / CV, cv = i - pp * CV;
            g_y2t[(size_t)(n0 + pp) * CV + cv] = tb[pp * 193 + cv];
        }
    }
}

// ---------------------------------------------------------------------------
// Padded-bin scatter (counts are zero at call entry; re-zeroed by interp).
// ---------------------------------------------------------------------------
__device__ __forceinline__ int bin_of(int batch, float x, float y, float z) {
    int bx = min(G - 1, max(0, (int)(x * 8.0f)));
    int by = min(G - 1, max(0, (int)(y * 8.0f)));
    int bz = min(G - 1, max(0, (int)(z * 8.0f)));
    return batch * NBIN + (bz * G + by) * G + bx;
}

__global__ void __launch_bounds__(256) bin_scatter_kernel(
    const float* __restrict__ p1, const float* __restrict__ p2)
{
    int t = blockIdx.x * 256 + threadIdx.x;
    if (t < N2TOT) {
        float x = p2[3 * t], y = p2[3 * t + 1], z = p2[3 * t + 2];
        int bin = bin_of(t >> 12, x, y, z);
        int pos = atomicAdd(&g_cnt2[bin], 1);
        if (pos < CAP2)
            g_bin2[bin][pos] = make_float4(x, y, z, __int_as_float(t & (N2PB - 1)));
    } else {
        int i = t - N2TOT;
        float x = p1[3 * i], y = p1[3 * i + 1], z = p1[3 * i + 2];
        int bin = bin_of(i >> 14, x, y, z);
        int pos = atomicAdd(&g_cnt1[bin], 1);
        if (pos < CAP1)
            g_bin1[bin][pos] = make_float4(x, y, z, __int_as_float(i));
    }
}

// ---------------------------------------------------------------------------
// 3-NN: warp-per-bin. All lanes of a warp share one query bin -> neighbor
// candidate loads are warp-uniform (broadcast). 3x3x3 scan + margin test +
// exact full-batch fallback. Strict-< insert (exact fp32).
// ---------------------------------------------------------------------------
__global__ void __launch_bounds__(128) knn_bin_kernel()
{
    const int w    = threadIdx.x >> 5;
    const int lane = threadIdx.x & 31;
    const int bin  = blockIdx.x * 4 + w;          // 512 blocks * 4 warps
    const int batch = bin >> 9;
    const int cell  = bin & (NBIN - 1);
    const int bx = cell & 7, by = (cell >> 3) & 7, bz = cell >> 6;
    const int cnt = min(g_cnt1[bin], CAP1);
    const int base = batch << 9;

    const int xlo = max(bx - 1, 0), xhi = min(bx + 1, G - 1);
    const int ylo = max(by - 1, 0), yhi = min(by + 1, G - 1);
    const int zlo = max(bz - 1, 0), zhi = min(bz + 1, G - 1);

    for (int t = lane; t < cnt; t += 32) {
        float4 q = g_bin1[bin][t];
        const int orig = __float_as_int(q.w);
        const float qx = q.x, qy = q.y, qz = q.z;

        float a0 = 3.4e38f, a1 = 3.4e38f, a2 = 3.4e38f;
        int   i0 = 0, i1 = 0, i2 = 0;

        for (int z = zlo; z <= zhi; z++) {
            for (int y = ylo; y <= yhi; y++) {
                for (int xx = xlo; xx <= xhi; xx++) {
                    int nb = base + (z * G + y) * G + xx;
                    int c2 = min(g_cnt2[nb], CAP2);
                    for (int j = 0; j < c2; j++) {
                        float4 c = g_bin2[nb][j];
                        float dx = qx - c.x, dy = qy - c.y, dz = qz - c.z;
                        float d2 = fmaf(dx, dx, fmaf(dy, dy, dz * dz));
                        int idx = __float_as_int(c.w);
                        bool c0 = d2 < a0, c1 = d2 < a1, cc2 = d2 < a2;
                        a2 = c1 ? a1 : (cc2 ? d2 : a2);  i2 = c1 ? i1 : (cc2 ? idx : i2);
                        a1 = c0 ? a0 : (c1 ? d2 : a1);   i1 = c0 ? i0 : (c1 ? idx : i1);
                        a0 = c0 ? d2 : a0;               i0 = c0 ? idx : i0;
                    }
                }
            }
        }

        // margin = distance to nearest unsearched in-domain region
        float margin = 3.4e38f;
        if (bx >= 2)     margin = fminf(margin, qx - (bx - 1) * BINW);
        if (bx <= G - 3) margin = fminf(margin, (bx + 2) * BINW - qx);
        if (by >= 2)     margin = fminf(margin, qy - (by - 1) * BINW);
        if (by <= G - 3) margin = fminf(margin, (by + 2) * BINW - qy);
        if (bz >= 2)     margin = fminf(margin, qz - (bz - 1) * BINW);
        if (bz <= G - 3) margin = fminf(margin, (bz + 2) * BINW - qz);

        if (a2 > margin * margin) {
            a0 = a1 = a2 = 3.4e38f; i0 = i1 = i2 = 0;
            for (int c = 0; c < NBIN; c++) {
                int nb = base + c;
                int c2 = min(g_cnt2[nb], CAP2);
                for (int j = 0; j < c2; j++) {
                    float4 cd = g_bin2[nb][j];
                    float dx = qx - cd.x, dy = qy - cd.y, dz = qz - cd.z;
                    float d2 = fmaf(dx, dx, fmaf(dy, dy, dz * dz));
                    int idx = __float_as_int(cd.w);
                    bool c0 = d2 < a0, c1 = d2 < a1, cc2 = d2 < a2;
                    a2 = c1 ? a1 : (cc2 ? d2 : a2);  i2 = c1 ? i1 : (cc2 ? idx : i2);
                    a1 = c0 ? a0 : (c1 ? d2 : a1);   i1 = c0 ? i0 : (c1 ? idx : i1);
                    a0 = c0 ? d2 : a0;               i0 = c0 ? idx : i0;
                }
            }
        }

        g_kd[0][orig] = a0; g_ki[0][orig] = i0;
        g_kd[1][orig] = a1; g_ki[1][orig] = i1;
        g_kd[2][orig] = a2; g_ki[2][orig] = i2;
    }
}

// ---------------------------------------------------------------------------
// Interp weights + gather + RMW into out. Also re-zeros bin counters
// (consumed by now) so the next call/replay starts from clean state.
// ---------------------------------------------------------------------------
__global__ void __launch_bounds__(256) interp_kernel(float* __restrict__ out)
{
    const int ng = blockIdx.x * 256 + threadIdx.x;
    if (ng < NBINT) g_cnt1[ng] = 0;
    else if (ng < 2 * NBINT) g_cnt2[ng - NBINT] = 0;
    const int batch = ng >> 14;

    float a0 = g_kd[0][ng], a1 = g_kd[1][ng], a2 = g_kd[2][ng];
    int   i0 = g_ki[0][ng], i1 = g_ki[1][ng], i2 = g_ki[2][ng];

    float w0 = 1.f / (a0 + 1e-8f);
    float w1 = 1.f / (a1 + 1e-8f);
    float w2 = 1.f / (a2 + 1e-8f);
    float inv = 1.f / (w0 + w1 + w2);
    w0 *= inv; w1 *= inv; w2 *= inv;

    const float4* f0 = (const float4*)(g_y2t + (size_t)(batch * N2PB + i0) * CV);
    const float4* f1 = (const float4*)(g_y2t + (size_t)(batch * N2PB + i1) * CV);
    const float4* f2 = (const float4*)(g_y2t + (size_t)(batch * N2PB + i2) * CV);
    float* op = out + ng;

#pragma unroll 4
    for (int c4 = 0; c4 < CV / 4; c4++) {
        float4 a = f0[c4], b = f1[c4], c = f2[c4];
        op[(size_t)(4 * c4 + 0) * N1TOT] += w0 * a.x + w1 * b.x + w2 * c.x;
        op[(size_t)(4 * c4 + 1) * N1TOT] += w0 * a.y + w1 * b.y + w2 * c.y;
        op[(size_t)(4 * c4 + 2) * N1TOT] += w0 * a.z + w1 * b.z + w2 * c.z;
        op[(size_t)(4 * c4 + 3) * N1TOT] += w0 * a.w + w1 * b.w + w2 * c.w;
    }
}

// ---------------------------------------------------------------------------
extern "C" void kernel_launch(void* const* d_in, const int* in_sizes, int n_in,
                              void* d_out, int out_size)
{
    const float* p1  = (const float*)d_in[0];
    const float* x1  = (const float*)d_in[1];
    const float* p2  = (const float*)d_in[3];
    const float* x2  = (const float*)d_in[4];
    const float* w1f = (const float*)d_in[6];
    const float* w1d = (const float*)d_in[7];
    const float* w2f = (const float*)d_in[8];
    const float* w2d = (const float*)d_in[9];
    float* out = (float*)d_out;

    const int SVN = 2 * BUFU * 8;   // 82944 B

    cudaFuncSetAttribute((const void*)vn_fused_kernel,
                         cudaFuncAttributeMaxDynamicSharedMemorySize, SVN);

    // VN layers (f32x2, double-buffered): [0,512): y2 ; [512,2560): y1
    vn_fused_kernel<<<2560, 256, SVN>>>(x1, w1f, w1d, x2, w2f, w2d, out);

    // Padded-bin scatter for p1 (queries) and p2 (candidates)
    bin_scatter_kernel<<<(N2TOT + N1TOT) / 256, 256>>>(p1, p2);

    // 3-NN: warp per query-bin
    knn_bin_kernel<<<NBINT / 4, 128>>>();

    // interpolation + add into out (also re-zeros counters)
    interp_kernel<<<N1TOT / 256, 256>>>(out);
}